// round 5
// baseline (speedup 1.0000x reference)
#include <cuda_runtime.h>

// ---------------- configuration ----------------
#define TN   128          // nodes per tile
#define SP   130          // activation row stride (floats), even (8B-aligned pairs)
#define KCH  8            // k rows per staged chunk (ping-pong)

// ---------------- shared memory layout (float offsets) ----------------
#define A256_OFF  0
#define A128_OFF  (256*SP)                   // 33280
#define STG0_OFF  (A128_OFF + 128*SP)        // 49920 (KCH*128 dup u64 = 2048 fl)
#define STG1_OFF  (STG0_OFF + KCH*128*2)     // 51968
#define C_B1      (STG1_OFF + KCH*128*2)     // 54016
#define C_BE1     (C_B1   + 256)
#define C_WE2     (C_BE1  + 128)             // 768 (128x6)
#define C_BE2     (C_WE2  + 768)             // 8 (6 used)
#define C_WD1D    (C_BE2  + 8)               // 1536: 6x128 duplicated (w,w)
#define C_BD1     (C_WD1D + 1536)
#define C_BD2     (C_BD1  + 128)
#define C_WO      (C_BD2  + 256)             // 256
#define C_BO      (C_WO   + 256)
#define SMEM_FLOATS (C_BO + 4)
#define SMEM_BYTES  (SMEM_FLOATS * 4)        // 229,440 B <= 232,448 opt-in

typedef unsigned long long u64t;

__device__ __forceinline__ void fma2(u64t& d, u64t a, u64t b) {
    asm("fma.rn.f32x2 %0, %1, %2, %0;" : "+l"(d) : "l"(a), "l"(b));
}
__device__ __forceinline__ void unpack2(u64t v, float& lo, float& hi) {
    asm("mov.b64 {%0, %1}, %2;" : "=f"(lo), "=f"(hi) : "l"(v));
}
// tanh(x) = 1 - 2/(e^{2x}+1): clamp-free, 2 MUFU + 3 fma-pipe, rel err ~1e-6
__device__ __forceinline__ float tanh_f(float x) {
    float e; asm("ex2.approx.f32 %0, %1;" : "=f"(e) : "f"(x * 2.885390082f));
    float r; asm("rcp.approx.f32 %0, %1;" : "=f"(r) : "f"(e + 1.0f));
    return fmaf(-2.0f, r, 1.0f);
}
// stage one float4 of W, duplicated (w,w) pairs, into stage buffer
__device__ __forceinline__ void dupstore(float* sm, int off, int srow, int sc4, float4 w) {
    float* p = &sm[off + (srow * 128 + sc4) * 2];
    *reinterpret_cast<float2*>(p + 0) = make_float2(w.x, w.x);
    *reinterpret_cast<float2*>(p + 2) = make_float2(w.y, w.y);
    *reinterpret_cast<float2*>(p + 4) = make_float2(w.z, w.z);
    *reinterpret_cast<float2*>(p + 6) = make_float2(w.w, w.w);
}

// ---------------- streamed GEMM over 128 output cols ----------------
// out[c][r] = (tanh?)( sum_k in[k][r] * W[k*ldw + coff + c] + bias[coff+c] )
// 256 threads: tx=tid&15 (cols tx+16j), ty=tid>>4 (rows r0=8ty, 4 f32x2 pairs).
// W staged PRE-DUPLICATED as (w,w) u64 -> B is one LDS.64, no pack.
// A loads are warp-broadcast (2 distinct ty/warp). Ping-pong, 1 barrier/stage.
template<int K, bool DOTANH>
__device__ __forceinline__ void gemm_stream(float* sm, int in_off,
        const float* __restrict__ W, int ldw, int coff, int bias_off, int out_off)
{
    const int tid = threadIdx.x;
    const int tx = tid & 15, ty = tid >> 4;
    const int r0 = ty * 8;
    const int srow = tid >> 5;           // 0..7 staging row within chunk
    const int sc4  = (tid & 31) * 4;     // 0,4,...,124 staging col quad

    u64t acc[4][8];
#pragma unroll
    for (int i = 0; i < 4; ++i)
#pragma unroll
        for (int j = 0; j < 8; ++j) acc[i][j] = 0ull;

    // prologue: stage chunk 0
    dupstore(sm, STG0_OFF, srow, sc4,
             *reinterpret_cast<const float4*>(&W[(size_t)srow * ldw + coff + sc4]));
    __syncthreads();

    const int NST = K / KCH;
#pragma unroll 1
    for (int s = 0; s < NST; ++s) {
        const float* buf = &sm[(s & 1) ? STG1_OFF : STG0_OFF];
        float4 wn;
        const bool have = (s + 1 < NST);
        if (have)
            wn = *reinterpret_cast<const float4*>(
                     &W[(size_t)((s + 1) * KCH + srow) * ldw + coff + sc4]);
#pragma unroll
        for (int kk = 0; kk < KCH; ++kk) {
            const float* A = &sm[in_off + (s * KCH + kk) * SP + r0];
            u64t a0 = *reinterpret_cast<const u64t*>(A + 0);
            u64t a1 = *reinterpret_cast<const u64t*>(A + 2);
            u64t a2 = *reinterpret_cast<const u64t*>(A + 4);
            u64t a3 = *reinterpret_cast<const u64t*>(A + 6);
            const float* B = buf + (kk * 128 + tx) * 2;
#pragma unroll
            for (int j = 0; j < 8; ++j) {
                u64t bb = *reinterpret_cast<const u64t*>(B + j * 32);
                fma2(acc[0][j], a0, bb);
                fma2(acc[1][j], a1, bb);
                fma2(acc[2][j], a2, bb);
                fma2(acc[3][j], a3, bb);
            }
        }
        if (have) dupstore(sm, (s & 1) ? STG0_OFF : STG1_OFF, srow, sc4, wn);
        __syncthreads();
    }
    // epilogue: bias (+tanh) -> feature-major out
#pragma unroll
    for (int j = 0; j < 8; ++j) {
        const int c = coff + tx + 16 * j;
        const float bias = sm[bias_off + c];
#pragma unroll
        for (int i = 0; i < 4; ++i) {
            float lo, hi; unpack2(acc[i][j], lo, hi);
            lo += bias; hi += bias;
            if (DOTANH) { lo = tanh_f(lo); hi = tanh_f(hi); }
            *reinterpret_cast<float2*>(&sm[out_off + c * SP + r0 + 2 * i]) =
                make_float2(lo, hi);
        }
    }
}

// ---------------- E2: 128 -> 6, tanh (z -> A256 rows 0..5) ----------------
__device__ __forceinline__ void layer_E2(float* sm)
{
    const int tid = threadIdx.x;
    const int r = tid & 127;
    const int g = tid >> 7;              // 0/1 -> outputs 3g..3g+2
    float a0 = 0.f, a1 = 0.f, a2 = 0.f;
#pragma unroll 8
    for (int k = 0; k < 128; ++k) {
        const float a = sm[A128_OFF + k * SP + r];
        const float* w = &sm[C_WE2 + k * 6 + g * 3];
        a0 = fmaf(a, w[0], a0);
        a1 = fmaf(a, w[1], a1);
        a2 = fmaf(a, w[2], a2);
    }
    const float* be = &sm[C_BE2 + g * 3];
    sm[A256_OFF + (g * 3 + 0) * SP + r] = tanh_f(a0 + be[0]);
    sm[A256_OFF + (g * 3 + 1) * SP + r] = tanh_f(a1 + be[1]);
    sm[A256_OFF + (g * 3 + 2) * SP + r] = tanh_f(a2 + be[2]);
}

// ---------------- D1: 6 -> 128, tanh (weights pre-duplicated) ----------------
__device__ __forceinline__ void layer_D1(float* sm)
{
    const int tid = threadIdx.x;
    const int tx = tid & 15, ty = tid >> 4;
    const int r0 = ty * 8;
    u64t acc[4][8];
#pragma unroll
    for (int i = 0; i < 4; ++i)
#pragma unroll
        for (int j = 0; j < 8; ++j) acc[i][j] = 0ull;
#pragma unroll
    for (int k = 0; k < 6; ++k) {
        const float* A = &sm[A256_OFF + k * SP + r0];
        u64t a0 = *reinterpret_cast<const u64t*>(A + 0);
        u64t a1 = *reinterpret_cast<const u64t*>(A + 2);
        u64t a2 = *reinterpret_cast<const u64t*>(A + 4);
        u64t a3 = *reinterpret_cast<const u64t*>(A + 6);
        const float* B = &sm[C_WD1D + (k * 128 + tx) * 2];
#pragma unroll
        for (int j = 0; j < 8; ++j) {
            u64t bb = *reinterpret_cast<const u64t*>(B + j * 32);
            fma2(acc[0][j], a0, bb);
            fma2(acc[1][j], a1, bb);
            fma2(acc[2][j], a2, bb);
            fma2(acc[3][j], a3, bb);
        }
    }
#pragma unroll
    for (int j = 0; j < 8; ++j) {
        const int c = tx + 16 * j;
        const float bias = sm[C_BD1 + c];
#pragma unroll
        for (int i = 0; i < 4; ++i) {
            float lo, hi; unpack2(acc[i][j], lo, hi);
            *reinterpret_cast<float2*>(&sm[A128_OFF + c * SP + r0 + 2 * i]) =
                make_float2(tanh_f(lo + bias), tanh_f(hi + bias));
        }
    }
}

// ---------------- O: out = sigmoid(tanh(d) @ Wo + bo) ----------------------
__device__ __forceinline__ void layer_O(float* sm, float* __restrict__ out,
                                        int nb, int Nn)
{
    const int tid = threadIdx.x;
    const int r = tid & 127;
    const int q = tid >> 7;              // k half 0/1
    float p = 0.f;
#pragma unroll 8
    for (int kk = 0; kk < 128; ++kk) {
        const int k = q * 128 + kk;
        p = fmaf(tanh_f(sm[A256_OFF + k * SP + r]), sm[C_WO + k], p);
    }
    sm[STG0_OFF + q * 128 + r] = p;      // stage buffer as scratch
    __syncthreads();
    if (q == 0) {
        const float v = sm[STG0_OFF + r] + sm[STG0_OFF + 128 + r] + sm[C_BO];
        float e;  asm("ex2.approx.f32 %0, %1;" : "=f"(e)  : "f"(-1.442695041f * v));
        float sg; asm("rcp.approx.f32 %0, %1;" : "=f"(sg) : "f"(1.0f + e));
        const int node = nb + r;
        if (node < Nn) out[node] = sg;
    }
}

// ---------------- main fused kernel ----------------
__global__ void __launch_bounds__(256, 1)
gnn_fused_kernel(const float* __restrict__ edge_attr,
                 const float* __restrict__ W1,  const float* __restrict__ b1,
                 const float* __restrict__ We1, const float* __restrict__ be1,
                 const float* __restrict__ We2, const float* __restrict__ be2,
                 const float* __restrict__ Wd1, const float* __restrict__ bd1,
                 const float* __restrict__ Wd2, const float* __restrict__ bd2,
                 const float* __restrict__ Wo,  const float* __restrict__ bo,
                 float* __restrict__ out, int Nn, int ntiles)
{
    extern __shared__ float sm[];
    const int tid = threadIdx.x;

    // cache constants once per block
    if (tid < 256) sm[C_B1  + tid] = b1[tid];
    if (tid < 128) sm[C_BE1 + tid] = be1[tid];
    for (int i = tid; i < 768; i += 256) sm[C_WE2 + i] = We2[i];
    if (tid < 6)   sm[C_BE2 + tid] = be2[tid];
    for (int i = tid; i < 768; i += 256) {          // Wd1 duplicated (w,w)
        const float w = Wd1[i];
        *reinterpret_cast<float2*>(&sm[C_WD1D + 2 * i]) = make_float2(w, w);
    }
    if (tid < 128) sm[C_BD1 + tid] = bd1[tid];
    if (tid < 256) sm[C_BD2 + tid] = bd2[tid];
    if (tid < 256) sm[C_WO  + tid] = Wo[tid];
    if (tid == 0)  sm[C_BO] = bo[0];

    for (int tile = blockIdx.x; tile < ntiles; tile += gridDim.x) {
        const int nb = tile * TN;
        __syncthreads();   // consts ready / prev-tile buffers consumed

        // load msgs tile (TN x 16) -> transposed [16][SP] in A128 region
#pragma unroll
        for (int q = 0; q < 2; ++q) {
            const int idx4 = tid + q * 256;       // 512 float4 = 2048 floats
            const int node = idx4 >> 2;
            const int kq   = (idx4 & 3) * 4;
            float4 v = make_float4(0.f, 0.f, 0.f, 0.f);
            if (nb + node < Nn)
                v = *reinterpret_cast<const float4*>(
                        &edge_attr[(size_t)(nb + node) * 16 + kq]);
            sm[A128_OFF + (kq + 0) * SP + node] = v.x;
            sm[A128_OFF + (kq + 1) * SP + node] = v.y;
            sm[A128_OFF + (kq + 2) * SP + node] = v.z;
            sm[A128_OFF + (kq + 3) * SP + node] = v.w;
        }
        __syncthreads();

        gemm_stream<16,  true >(sm, A128_OFF, W1,  256, 0,   C_B1,  A256_OFF); // L1 lo
        gemm_stream<16,  true >(sm, A128_OFF, W1,  256, 128, C_B1,  A256_OFF); // L1 hi
        __syncthreads();
        gemm_stream<256, true >(sm, A256_OFF, We1, 128, 0,   C_BE1, A128_OFF); // E1
        __syncthreads();
        layer_E2(sm);                                                          // -> z
        __syncthreads();
        layer_D1(sm);                                                          // -> A128
        __syncthreads();
        gemm_stream<128, false>(sm, A128_OFF, Wd2, 256, 0,   C_BD2, A256_OFF); // D2 lo
        gemm_stream<128, false>(sm, A128_OFF, Wd2, 256, 128, C_BD2, A256_OFF); // D2 hi
        __syncthreads();
        layer_O(sm, out, nb, Nn);
    }
}

// ---------------- launch ----------------
extern "C" void kernel_launch(void* const* d_in, const int* in_sizes, int n_in,
                              void* d_out, int out_size)
{
    const float* edge_attr = (const float*)d_in[2];
    const float* W1  = (const float*)d_in[3];
    const float* b1  = (const float*)d_in[4];
    const float* We1 = (const float*)d_in[5];
    const float* be1 = (const float*)d_in[6];
    const float* We2 = (const float*)d_in[7];
    const float* be2 = (const float*)d_in[8];
    const float* Wd1 = (const float*)d_in[9];
    const float* bd1 = (const float*)d_in[10];
    const float* Wd2 = (const float*)d_in[11];
    const float* bd2 = (const float*)d_in[12];
    const float* Wo  = (const float*)d_in[13];
    const float* bo  = (const float*)d_in[14];
    float* out = (float*)d_out;

    const int Nn = out_size;
    const int ntiles = (Nn + TN - 1) / TN;

    cudaFuncSetAttribute(gnn_fused_kernel,
                         cudaFuncAttributeMaxDynamicSharedMemorySize, SMEM_BYTES);
    int sms = 148;
    cudaDeviceGetAttribute(&sms, cudaDevAttrMultiProcessorCount, 0);
    const int grid = ntiles < sms ? ntiles : sms;

    gnn_fused_kernel<<<grid, 256, SMEM_BYTES>>>(
        edge_attr, W1, b1, We1, be1, We2, be2, Wd1, bd1, Wd2, bd2, Wo, bo,
        out, Nn, ntiles);
}

// round 7
// speedup vs baseline: 1.7282x; 1.7282x over previous
#include <cuda_runtime.h>
#include <cuda_bf16.h>

typedef unsigned int u32;

// ---------------- smem layout (bytes) ----------------
// A region: h planes [128][264]bf16 hi@0 lo@67584 ; later d planes [128][136] hi@0 lo@34816
#define SM_A    0
#define H_LO    67584
#define D_LO    34816
// B region (staging): L1 -> msgs hi/lo + W1t hi/lo ; E1 chunk [128][136]x2 ; D2 chunk [256][72]x2
#define SM_B    135168
#define MS_HI   (SM_B)
#define MS_LO   (SM_B + 6144)
#define W1_HI   (SM_B + 12288)
#define W1_LO   (SM_B + 24576)
#define EB_LO   34816            /* relative to SM_B */
#define DB_LO   36864            /* relative to SM_B */
#define SM_C    (SM_B + 73728)
// const region (float offsets from SM_C)
#define CF_B1   0
#define CF_BE1  256
#define CF_WE2  384
#define CF_BE2  1152
#define CF_WD1  1160
#define CF_BD1  1928
#define CF_BD2  2056
#define CF_WO   2312
#define CF_BO   2568
#define CF_ZP   2572             /* 2*128*6 */
#define CF_OP   4108             /* 2*128 */
#define CF_TOT  4364
#define SMEM_BYTES (SM_C + CF_TOT*4)   /* 226,352 <= 232,448 opt-in */

// pitches (bytes): pad K by 8 bf16 -> conflict-free ldmatrix row addressing
#define P_MS  48     /* msgs / W1t: K=16+8 */
#define P_H   528    /* h: K=256+8 */
#define P_D   272    /* d / E1-B chunk: K=128+8 */
#define P_DB  144    /* D2-B chunk: K=64+8 */

// ---------------- pre-split/transposed bf16 weight images ----------------
__device__ __align__(16) unsigned char g_W1t[24576];    // [256n][24k] hi | lo
__device__ __align__(16) unsigned char g_We1t[139264];  // 2 x ([128n][136k] hi | lo)
__device__ __align__(16) unsigned char g_Wd2t[147456];  // 2 x ([256n][72k]  hi | lo)

// ---------------- helpers ----------------
__device__ __forceinline__ u32 smem_u32(const void* p) {
    u32 a;
    asm("{ .reg .u64 t; cvta.to.shared.u64 t, %1; cvt.u32.u64 %0, t; }"
        : "=r"(a) : "l"(p));
    return a;
}
__device__ __forceinline__ void ldmx4(u32& r0, u32& r1, u32& r2, u32& r3, u32 addr) {
    asm volatile("ldmatrix.sync.aligned.m8n8.x4.shared.b16 {%0,%1,%2,%3}, [%4];"
                 : "=r"(r0), "=r"(r1), "=r"(r2), "=r"(r3) : "r"(addr));
}
__device__ __forceinline__ void mma16816(float* c, u32 a0, u32 a1, u32 a2, u32 a3,
                                         u32 b0, u32 b1) {
    asm volatile("mma.sync.aligned.m16n8k16.row.col.f32.bf16.bf16.f32 "
                 "{%0,%1,%2,%3}, {%4,%5,%6,%7}, {%8,%9}, {%0,%1,%2,%3};"
                 : "+f"(c[0]), "+f"(c[1]), "+f"(c[2]), "+f"(c[3])
                 : "r"(a0), "r"(a1), "r"(a2), "r"(a3), "r"(b0), "r"(b1));
}
// tanh(x) = 1 - 2/(e^{2x}+1), rel err ~1e-6
__device__ __forceinline__ float tanh_f(float x) {
    float e; asm("ex2.approx.f32 %0, %1;" : "=f"(e) : "f"(x * 2.885390082f));
    float r; asm("rcp.approx.f32 %0, %1;" : "=f"(r) : "f"(e + 1.0f));
    return fmaf(-2.0f, r, 1.0f);
}
__device__ __forceinline__ u32 pack_split(float x0, float x1, u32& lo) {
    __nv_bfloat16 h0 = __float2bfloat16(x0), h1 = __float2bfloat16(x1);
    __nv_bfloat16 l0 = __float2bfloat16(x0 - __bfloat162float(h0));
    __nv_bfloat16 l1 = __float2bfloat16(x1 - __bfloat162float(h1));
    lo = (u32)__bfloat16_as_ushort(l0) | ((u32)__bfloat16_as_ushort(l1) << 16);
    return (u32)__bfloat16_as_ushort(h0) | ((u32)__bfloat16_as_ushort(h1) << 16);
}
__device__ __forceinline__ void wsplit(unsigned char* hi, unsigned char* lo, float v) {
    __nv_bfloat16 h = __float2bfloat16(v);
    __nv_bfloat16 l = __float2bfloat16(v - __bfloat162float(h));
    *(__nv_bfloat16*)hi = h;
    *(__nv_bfloat16*)lo = l;
}

// ---------------- prep: transpose + split weights into smem-image layout ----
__global__ void prep_weights(const float* __restrict__ W1,
                             const float* __restrict__ We1,
                             const float* __restrict__ Wd2)
{
    int idx = blockIdx.x * 256 + threadIdx.x;
    if (idx < 6144) {                              // W1t: [256n][24k]
        int n = idx / 24, k = idx % 24;
        float v = (k < 16) ? W1[k * 256 + n] : 0.f;
        wsplit(g_W1t + n * P_MS + k * 2, g_W1t + 12288 + n * P_MS + k * 2, v);
        return;
    }
    idx -= 6144;
    if (idx < 34816) {                             // We1t: 2 x [128n][136k]
        int c = idx / 17408, rst = idx % 17408;
        int n = rst / 136, kk = rst % 136;
        float v = (kk < 128) ? We1[(c * 128 + kk) * 128 + n] : 0.f;
        int base = c * 69632 + n * P_D + kk * 2;
        wsplit(g_We1t + base, g_We1t + base + EB_LO, v);
        return;
    }
    idx -= 34816;
    if (idx < 36864) {                             // Wd2t: 2 x [256n][72k]
        int c = idx / 18432, rst = idx % 18432;
        int n = rst / 72, kk = rst % 72;
        float v = (kk < 64) ? Wd2[(c * 64 + kk) * 256 + n] : 0.f;
        int base = c * 73728 + n * P_DB + kk * 2;
        wsplit(g_Wd2t + base, g_Wd2t + base + DB_LO, v);
    }
}

// ---------------- warp GEMM: 32 rows x (NPAIRS*16) cols, KSTEPS k16-steps ----
template<int KSTEPS, int NPAIRS>
__device__ __forceinline__ void wgemm(float* acc, u32 aBase, int aPitch,
                                      u32 bBase, int bPitch)
{
    const int lane = threadIdx.x & 31;
    const u32 aAddr = aBase + (u32)((lane & 15) * aPitch + ((lane >> 4) << 4));
    const int q = lane >> 3;
    const u32 bAddr = bBase + (u32)((((q >> 1) << 3) + (lane & 7)) * bPitch
                                    + ((q & 1) << 4));
#pragma unroll
    for (int ks = 0; ks < KSTEPS; ++ks) {
        u32 a0, a1, a2, a3, a4, a5, a6, a7;
        ldmx4(a0, a1, a2, a3, aAddr + ks * 32);
        ldmx4(a4, a5, a6, a7, aAddr + 16 * aPitch + ks * 32);
#pragma unroll
        for (int np = 0; np < NPAIRS; ++np) {
            u32 b0, b1, b2, b3;
            ldmx4(b0, b1, b2, b3, bAddr + np * 16 * bPitch + ks * 32);
            mma16816(acc + (0 * 2 * NPAIRS + 2 * np + 0) * 4, a0, a1, a2, a3, b0, b1);
            mma16816(acc + (0 * 2 * NPAIRS + 2 * np + 1) * 4, a0, a1, a2, a3, b2, b3);
            mma16816(acc + (1 * 2 * NPAIRS + 2 * np + 0) * 4, a4, a5, a6, a7, b0, b1);
            mma16816(acc + (1 * 2 * NPAIRS + 2 * np + 1) * 4, a4, a5, a6, a7, b2, b3);
        }
    }
}

__device__ __forceinline__ void cpy16(unsigned char* dst, const unsigned char* src,
                                      int n16, int tid)
{
    const uint4* s = (const uint4*)src;
    uint4* d = (uint4*)dst;
    for (int i = tid; i < n16; i += 256) d[i] = s[i];
}

// ---------------- main fused kernel ----------------
__global__ void __launch_bounds__(256, 1)
gnn_mma_kernel(const float* __restrict__ edge_attr,
               const float* __restrict__ b1,  const float* __restrict__ be1,
               const float* __restrict__ We2, const float* __restrict__ be2,
               const float* __restrict__ Wd1, const float* __restrict__ bd1,
               const float* __restrict__ bd2, const float* __restrict__ Wo,
               const float* __restrict__ bo,
               float* __restrict__ out, int Nn, int ntiles)
{
    extern __shared__ unsigned char smem[];
    float* cf = (float*)(smem + SM_C);
    const int tid = threadIdx.x;
    const int w = tid >> 5, lane = tid & 31;
    const int g = lane >> 2, t = lane & 3;
    const int warpM = (w & 3) * 32;
    const int ngrp = w >> 2;
    const int wN256 = ngrp * 128, wN128 = ngrp * 64;
    const u32 sb = smem_u32(smem);

    // constants
    if (tid < 256) cf[CF_B1 + tid] = b1[tid];
    if (tid < 128) cf[CF_BE1 + tid] = be1[tid];
    for (int i = tid; i < 768; i += 256) cf[CF_WE2 + i] = We2[i];
    if (tid < 6)   cf[CF_BE2 + tid] = be2[tid];
    for (int i = tid; i < 768; i += 256) cf[CF_WD1 + i] = Wd1[i];
    if (tid < 128) cf[CF_BD1 + tid] = bd1[tid];
    if (tid < 256) cf[CF_BD2 + tid] = bd2[tid];
    if (tid < 256) cf[CF_WO  + tid] = Wo[tid];
    if (tid == 0)  cf[CF_BO] = bo[0];

    for (int tile = blockIdx.x; tile < ntiles; tile += gridDim.x) {
        const int nb = tile * 128;
        __syncthreads();                      // prev tile fully consumed

        // ---- msgs -> split planes; W1 images -> smem ----
        if (tid < 128) {
            float f[16];
            const int node = nb + tid;
            if (node < Nn) {
                const float4* p = (const float4*)(edge_attr + (size_t)node * 16);
#pragma unroll
                for (int q4 = 0; q4 < 4; ++q4) {
                    float4 v = p[q4];
                    f[4*q4+0]=v.x; f[4*q4+1]=v.y; f[4*q4+2]=v.z; f[4*q4+3]=v.w;
                }
            } else {
#pragma unroll
                for (int i = 0; i < 16; ++i) f[i] = 0.f;
            }
#pragma unroll
            for (int kp = 0; kp < 8; ++kp) {
                u32 lo; u32 hi = pack_split(f[2*kp], f[2*kp+1], lo);
                *(u32*)(smem + MS_HI + tid * P_MS + kp * 4) = hi;
                *(u32*)(smem + MS_LO + tid * P_MS + kp * 4) = lo;
            }
        }
        cpy16(smem + W1_HI, g_W1t, 1536, tid);   // hi+lo contiguous
        __syncthreads();

        // ---- L1: [128x16] @ [16x256] -> h ----
        {
            float acc[128];
#pragma unroll
            for (int i = 0; i < 128; ++i) acc[i] = 0.f;
#pragma unroll
            for (int p = 0; p < 3; ++p)
                wgemm<1, 8>(acc,
                    sb + MS_HI + (p == 1 ? 6144u : 0u) + warpM * P_MS, P_MS,
                    sb + W1_HI + (p == 2 ? 12288u : 0u) + wN256 * P_MS, P_MS);
            // epilogue: bias+tanh+split -> h planes
#pragma unroll
            for (int im = 0; im < 2; ++im)
#pragma unroll
            for (int jn = 0; jn < 16; ++jn) {
                const int idx = (im * 16 + jn) * 4;
                const int c = wN256 + 8 * jn + 2 * t;
                const int r = warpM + 16 * im + g;
                u32 lo;
                u32 hi = pack_split(tanh_f(acc[idx+0] + cf[CF_B1 + c]),
                                    tanh_f(acc[idx+1] + cf[CF_B1 + c + 1]), lo);
                *(u32*)(smem + SM_A + r * P_H + c * 2) = hi;
                *(u32*)(smem + SM_A + H_LO + r * P_H + c * 2) = lo;
                hi = pack_split(tanh_f(acc[idx+2] + cf[CF_B1 + c]),
                                tanh_f(acc[idx+3] + cf[CF_B1 + c + 1]), lo);
                *(u32*)(smem + SM_A + (r + 8) * P_H + c * 2) = hi;
                *(u32*)(smem + SM_A + H_LO + (r + 8) * P_H + c * 2) = lo;
            }
        }
        __syncthreads();

        // ---- E1: [128x256] @ [256x128], K chunked by 128 ----
        {
            float acc[64];
#pragma unroll
            for (int i = 0; i < 64; ++i) acc[i] = 0.f;
            for (int c = 0; c < 2; ++c) {
                cpy16(smem + SM_B, g_We1t + c * 69632, 4352, tid);
                __syncthreads();
#pragma unroll
                for (int p = 0; p < 3; ++p)
                    wgemm<8, 4>(acc,
                        sb + SM_A + (p == 1 ? (u32)H_LO : 0u) + warpM * P_H + c * 256, P_H,
                        sb + SM_B + (p == 2 ? (u32)EB_LO : 0u) + wN128 * P_D, P_D);
                __syncthreads();
            }
            // epilogue: tanh -> z partials (E2)
            float zp[24];
#pragma unroll
            for (int i = 0; i < 24; ++i) zp[i] = 0.f;
#pragma unroll
            for (int im = 0; im < 2; ++im)
#pragma unroll
            for (int jn = 0; jn < 8; ++jn) {
                const int idx = (im * 8 + jn) * 4;
                const int c = wN128 + 8 * jn + 2 * t;
                const float h0 = tanh_f(acc[idx+0] + cf[CF_BE1 + c]);
                const float h1 = tanh_f(acc[idx+1] + cf[CF_BE1 + c + 1]);
                const float h2 = tanh_f(acc[idx+2] + cf[CF_BE1 + c]);
                const float h3 = tanh_f(acc[idx+3] + cf[CF_BE1 + c + 1]);
                const float* w0 = &cf[CF_WE2 + c * 6];
                const float* w1 = &cf[CF_WE2 + (c + 1) * 6];
#pragma unroll
                for (int j = 0; j < 6; ++j) {
                    zp[(im*2+0)*6+j] += h0 * w0[j] + h1 * w1[j];
                    zp[(im*2+1)*6+j] += h2 * w0[j] + h3 * w1[j];
                }
            }
#pragma unroll
            for (int i = 0; i < 24; ++i) {
                zp[i] += __shfl_xor_sync(0xffffffffu, zp[i], 1);
                zp[i] += __shfl_xor_sync(0xffffffffu, zp[i], 2);
            }
            if (t == 0) {
#pragma unroll
                for (int im = 0; im < 2; ++im)
#pragma unroll
                for (int rh = 0; rh < 2; ++rh) {
                    const int r = warpM + 16 * im + 8 * rh + g;
#pragma unroll
                    for (int j = 0; j < 6; ++j)
                        cf[CF_ZP + (ngrp * 128 + r) * 6 + j] = zp[(im*2+rh)*6+j];
                }
            }
        }
        __syncthreads();

        // ---- E2 finish + D1: z -> d planes (scalar, tiny) ----
        {
            const int r = tid >> 1;
            const int ih = (tid & 1) * 64;
            float z[6];
#pragma unroll
            for (int j = 0; j < 6; ++j)
                z[j] = tanh_f(cf[CF_ZP + r * 6 + j] + cf[CF_ZP + 768 + r * 6 + j]
                              + cf[CF_BE2 + j]);
#pragma unroll 8
            for (int i = ih; i < ih + 64; i += 2) {
                float d0 = cf[CF_BD1 + i], d1 = cf[CF_BD1 + i + 1];
#pragma unroll
                for (int j = 0; j < 6; ++j) {
                    d0 = fmaf(z[j], cf[CF_WD1 + j * 128 + i],     d0);
                    d1 = fmaf(z[j], cf[CF_WD1 + j * 128 + i + 1], d1);
                }
                u32 lo; u32 hi = pack_split(tanh_f(d0), tanh_f(d1), lo);
                *(u32*)(smem + SM_A + r * P_D + i * 2) = hi;
                *(u32*)(smem + SM_A + D_LO + r * P_D + i * 2) = lo;
            }
        }
        __syncthreads();

        // ---- D2: [128x128] @ [128x256], K chunked by 64 ----
        {
            float acc[128];
#pragma unroll
            for (int i = 0; i < 128; ++i) acc[i] = 0.f;
            for (int c = 0; c < 2; ++c) {
                cpy16(smem + SM_B, g_Wd2t + c * 73728, 4608, tid);
                __syncthreads();
#pragma unroll
                for (int p = 0; p < 3; ++p)
                    wgemm<4, 8>(acc,
                        sb + SM_A + (p == 1 ? (u32)D_LO : 0u) + warpM * P_D + c * 128, P_D,
                        sb + SM_B + (p == 2 ? (u32)DB_LO : 0u) + wN256 * P_DB, P_DB);
                __syncthreads();
            }
            // epilogue: O-layer row partial sums
            float op[4] = {0.f, 0.f, 0.f, 0.f};
#pragma unroll
            for (int im = 0; im < 2; ++im)
#pragma unroll
            for (int jn = 0; jn < 16; ++jn) {
                const int idx = (im * 16 + jn) * 4;
                const int c = wN256 + 8 * jn + 2 * t;
                op[im*2+0] += tanh_f(acc[idx+0] + cf[CF_BD2 + c])     * cf[CF_WO + c]
                            + tanh_f(acc[idx+1] + cf[CF_BD2 + c + 1]) * cf[CF_WO + c + 1];
                op[im*2+1] += tanh_f(acc[idx+2] + cf[CF_BD2 + c])     * cf[CF_WO + c]
                            + tanh_f(acc[idx+3] + cf[CF_BD2 + c + 1]) * cf[CF_WO + c + 1];
            }
#pragma unroll
            for (int i = 0; i < 4; ++i) {
                op[i] += __shfl_xor_sync(0xffffffffu, op[i], 1);
                op[i] += __shfl_xor_sync(0xffffffffu, op[i], 2);
            }
            if (t == 0) {
#pragma unroll
                for (int im = 0; im < 2; ++im)
#pragma unroll
                for (int rh = 0; rh < 2; ++rh)
                    cf[CF_OP + ngrp * 128 + warpM + 16 * im + 8 * rh + g] = op[im*2+rh];
            }
        }
        __syncthreads();

        if (tid < 128) {
            const float v = cf[CF_OP + tid] + cf[CF_OP + 128 + tid] + cf[CF_BO];
            float e;  asm("ex2.approx.f32 %0, %1;" : "=f"(e)  : "f"(-1.442695041f * v));
            float sg; asm("rcp.approx.f32 %0, %1;" : "=f"(sg) : "f"(1.0f + e));
            if (nb + tid < Nn) out[nb + tid] = sg;
        }
    }
}

// ---------------- launch ----------------
extern "C" void kernel_launch(void* const* d_in, const int* in_sizes, int n_in,
                              void* d_out, int out_size)
{
    // order: x, edge_index, edge_attr, W1, b1, We1, be1, We2, be2,
    //        Wd1, bd1, Wd2, bd2, Wo, bo
    const float* edge_attr = (const float*)d_in[2];
    const float* W1  = (const float*)d_in[3];
    const float* b1  = (const float*)d_in[4];
    const float* We1 = (const float*)d_in[5];
    const float* be1 = (const float*)d_in[6];
    const float* We2 = (const float*)d_in[7];
    const float* be2 = (const float*)d_in[8];
    const float* Wd1 = (const float*)d_in[9];
    const float* bd1 = (const float*)d_in[10];
    const float* Wd2 = (const float*)d_in[11];
    const float* bd2 = (const float*)d_in[12];
    const float* Wo  = (const float*)d_in[13];
    const float* bo  = (const float*)d_in[14];
    float* out = (float*)d_out;

    const int Nn = out_size;
    const int ntiles = (Nn + 127) / 128;

    prep_weights<<<304, 256>>>(W1, We1, Wd2);   // 77824 elements

    cudaFuncSetAttribute(gnn_mma_kernel,
                         cudaFuncAttributeMaxDynamicSharedMemorySize, SMEM_BYTES);
    int sms = 148;
    cudaDeviceGetAttribute(&sms, cudaDevAttrMultiProcessorCount, 0);
    const int grid = ntiles < sms ? ntiles : sms;

    gnn_mma_kernel<<<grid, 256, SMEM_BYTES>>>(
        edge_attr, b1, be1, We2, be2, Wd1, bd1, bd2, Wo, bo, out, Nn, ntiles);
}

// round 8
// speedup vs baseline: 1.7365x; 1.0048x over previous
#include <cuda_runtime.h>
#include <cuda_bf16.h>

typedef unsigned int u32;

// ---------------- smem layout (bytes) ----------------
// A region: h planes [128][264]bf16 hi@0 lo@67584 ; later d planes [128][136] hi@0 lo@34816
#define SM_A    0
#define H_LO    67584
#define D_LO    34816
// B region (staging): L1 -> msgs hi/lo + W1t hi/lo ; E1 chunk [128][136]x2 ; D2 chunk [256][72]x2
#define SM_B    135168
#define MS_HI   (SM_B)
#define MS_LO   (SM_B + 6144)
#define W1_HI   (SM_B + 12288)
#define W1_LO   (SM_B + 24576)
#define EB_LO   34816            /* relative to SM_B */
#define DB_LO   36864            /* relative to SM_B */
#define SM_C    (SM_B + 73728)
// const region (float offsets from SM_C)
#define CF_B1   0
#define CF_BE1  256
#define CF_WE2  384
#define CF_BE2  1152
#define CF_WD1  1160
#define CF_BD1  1928
#define CF_BD2  2056
#define CF_WO   2312
#define CF_BO   2568
#define CF_ZP   2572             /* 2*128*6 */
#define CF_OP   4108             /* 2*128 */
#define CF_TOT  4364
#define SMEM_BYTES (SM_C + CF_TOT*4)   /* 226,352 <= 232,448 opt-in */

// pitches (bytes): pad K by 8 bf16 -> conflict-free ldmatrix row addressing
#define P_MS  48     /* msgs / W1t: K=16+8 */
#define P_H   528    /* h: K=256+8 */
#define P_D   272    /* d / E1-B chunk: K=128+8 */
#define P_DB  144    /* D2-B chunk: K=64+8 */

// ---------------- pre-split/transposed bf16 weight images ----------------
__device__ __align__(16) unsigned char g_W1t[24576];    // [256n][24k] hi | lo
__device__ __align__(16) unsigned char g_We1t[139264];  // 2 x ([128n][136k] hi | lo)
__device__ __align__(16) unsigned char g_Wd2t[147456];  // 2 x ([256n][72k]  hi | lo)

// ---------------- helpers ----------------
__device__ __forceinline__ u32 smem_u32(const void* p) {
    u32 a;
    asm("{ .reg .u64 t; cvta.to.shared.u64 t, %1; cvt.u32.u64 %0, t; }"
        : "=r"(a) : "l"(p));
    return a;
}
__device__ __forceinline__ void ldmx4(u32& r0, u32& r1, u32& r2, u32& r3, u32 addr) {
    asm volatile("ldmatrix.sync.aligned.m8n8.x4.shared.b16 {%0,%1,%2,%3}, [%4];"
                 : "=r"(r0), "=r"(r1), "=r"(r2), "=r"(r3) : "r"(addr));
}
__device__ __forceinline__ void mma16816(float* c, u32 a0, u32 a1, u32 a2, u32 a3,
                                         u32 b0, u32 b1) {
    asm volatile("mma.sync.aligned.m16n8k16.row.col.f32.bf16.bf16.f32 "
                 "{%0,%1,%2,%3}, {%4,%5,%6,%7}, {%8,%9}, {%0,%1,%2,%3};"
                 : "+f"(c[0]), "+f"(c[1]), "+f"(c[2]), "+f"(c[3])
                 : "r"(a0), "r"(a1), "r"(a2), "r"(a3), "r"(b0), "r"(b1));
}
// tanh(x) = 1 - 2/(e^{2x}+1), rel err ~1e-6
__device__ __forceinline__ float tanh_f(float x) {
    float e; asm("ex2.approx.f32 %0, %1;" : "=f"(e) : "f"(x * 2.885390082f));
    float r; asm("rcp.approx.f32 %0, %1;" : "=f"(r) : "f"(e + 1.0f));
    return fmaf(-2.0f, r, 1.0f);
}
__device__ __forceinline__ u32 pack_split(float x0, float x1, u32& lo) {
    __nv_bfloat16 h0 = __float2bfloat16(x0), h1 = __float2bfloat16(x1);
    __nv_bfloat16 l0 = __float2bfloat16(x0 - __bfloat162float(h0));
    __nv_bfloat16 l1 = __float2bfloat16(x1 - __bfloat162float(h1));
    lo = (u32)__bfloat16_as_ushort(l0) | ((u32)__bfloat16_as_ushort(l1) << 16);
    return (u32)__bfloat16_as_ushort(h0) | ((u32)__bfloat16_as_ushort(h1) << 16);
}
__device__ __forceinline__ void wsplit(unsigned char* hi, unsigned char* lo, float v) {
    __nv_bfloat16 h = __float2bfloat16(v);
    __nv_bfloat16 l = __float2bfloat16(v - __bfloat162float(h));
    *(__nv_bfloat16*)hi = h;
    *(__nv_bfloat16*)lo = l;
}

// ---------------- prep: transpose + split weights into smem-image layout ----
__global__ void prep_weights(const float* __restrict__ W1,
                             const float* __restrict__ We1,
                             const float* __restrict__ Wd2)
{
    int idx = blockIdx.x * 256 + threadIdx.x;
    if (idx < 6144) {                              // W1t: [256n][24k]
        int n = idx / 24, k = idx % 24;
        float v = (k < 16) ? W1[k * 256 + n] : 0.f;
        wsplit(g_W1t + n * P_MS + k * 2, g_W1t + 12288 + n * P_MS + k * 2, v);
        return;
    }
    idx -= 6144;
    if (idx < 34816) {                             // We1t: 2 x [128n][136k]
        int c = idx / 17408, rst = idx % 17408;
        int n = rst / 136, kk = rst % 136;
        float v = (kk < 128) ? We1[(c * 128 + kk) * 128 + n] : 0.f;
        int base = c * 69632 + n * P_D + kk * 2;
        wsplit(g_We1t + base, g_We1t + base + EB_LO, v);
        return;
    }
    idx -= 34816;
    if (idx < 36864) {                             // Wd2t: 2 x [256n][72k]
        int c = idx / 18432, rst = idx % 18432;
        int n = rst / 72, kk = rst % 72;
        float v = (kk < 64) ? Wd2[(c * 64 + kk) * 256 + n] : 0.f;
        int base = c * 73728 + n * P_DB + kk * 2;
        wsplit(g_Wd2t + base, g_Wd2t + base + DB_LO, v);
    }
}

// ---------------- warp GEMM: 32 rows x (NPAIRS*16) cols, KSTEPS k16-steps ----
template<int KSTEPS, int NPAIRS>
__device__ __forceinline__ void wgemm(float* acc, u32 aBase, int aPitch,
                                      u32 bBase, int bPitch)
{
    const int lane = threadIdx.x & 31;
    const u32 aAddr = aBase + (u32)((lane & 15) * aPitch + ((lane >> 4) << 4));
    const int q = lane >> 3;
    const u32 bAddr = bBase + (u32)((((q >> 1) << 3) + (lane & 7)) * bPitch
                                    + ((q & 1) << 4));
#pragma unroll
    for (int ks = 0; ks < KSTEPS; ++ks) {
        u32 a0, a1, a2, a3, a4, a5, a6, a7;
        ldmx4(a0, a1, a2, a3, aAddr + ks * 32);
        ldmx4(a4, a5, a6, a7, aAddr + 16 * aPitch + ks * 32);
#pragma unroll
        for (int np = 0; np < NPAIRS; ++np) {
            u32 b0, b1, b2, b3;
            ldmx4(b0, b1, b2, b3, bAddr + np * 16 * bPitch + ks * 32);
            mma16816(acc + (0 * 2 * NPAIRS + 2 * np + 0) * 4, a0, a1, a2, a3, b0, b1);
            mma16816(acc + (0 * 2 * NPAIRS + 2 * np + 1) * 4, a0, a1, a2, a3, b2, b3);
            mma16816(acc + (1 * 2 * NPAIRS + 2 * np + 0) * 4, a4, a5, a6, a7, b0, b1);
            mma16816(acc + (1 * 2 * NPAIRS + 2 * np + 1) * 4, a4, a5, a6, a7, b2, b3);
        }
    }
}

__device__ __forceinline__ void cpy16(unsigned char* dst, const unsigned char* src,
                                      int n16, int tid)
{
    const uint4* s = (const uint4*)src;
    uint4* d = (uint4*)dst;
    for (int i = tid; i < n16; i += 256) d[i] = s[i];
}

// ---------------- main fused kernel ----------------
__global__ void __launch_bounds__(256, 1)
gnn_mma_kernel(const float* __restrict__ edge_attr,
               const float* __restrict__ b1,  const float* __restrict__ be1,
               const float* __restrict__ We2, const float* __restrict__ be2,
               const float* __restrict__ Wd1, const float* __restrict__ bd1,
               const float* __restrict__ bd2, const float* __restrict__ Wo,
               const float* __restrict__ bo,
               float* __restrict__ out, int Nn, int ntiles)
{
    extern __shared__ unsigned char smem[];
    float* cf = (float*)(smem + SM_C);
    const int tid = threadIdx.x;
    const int w = tid >> 5, lane = tid & 31;
    const int g = lane >> 2, t = lane & 3;
    const int warpM = (w & 3) * 32;
    const int ngrp = w >> 2;
    const int wN256 = ngrp * 128, wN128 = ngrp * 64;
    const u32 sb = smem_u32(smem);

    // constants
    if (tid < 256) cf[CF_B1 + tid] = b1[tid];
    if (tid < 128) cf[CF_BE1 + tid] = be1[tid];
    for (int i = tid; i < 768; i += 256) cf[CF_WE2 + i] = We2[i];
    if (tid < 6)   cf[CF_BE2 + tid] = be2[tid];
    for (int i = tid; i < 768; i += 256) cf[CF_WD1 + i] = Wd1[i];
    if (tid < 128) cf[CF_BD1 + tid] = bd1[tid];
    if (tid < 256) cf[CF_BD2 + tid] = bd2[tid];
    if (tid < 256) cf[CF_WO  + tid] = Wo[tid];
    if (tid == 0)  cf[CF_BO] = bo[0];

    for (int tile = blockIdx.x; tile < ntiles; tile += gridDim.x) {
        const int nb = tile * 128;
        __syncthreads();                      // prev tile fully consumed

        // ---- msgs -> split planes; W1 images -> smem ----
        if (tid < 128) {
            float f[16];
            const int node = nb + tid;
            if (node < Nn) {
                const float4* p = (const float4*)(edge_attr + (size_t)node * 16);
#pragma unroll
                for (int q4 = 0; q4 < 4; ++q4) {
                    float4 v = p[q4];
                    f[4*q4+0]=v.x; f[4*q4+1]=v.y; f[4*q4+2]=v.z; f[4*q4+3]=v.w;
                }
            } else {
#pragma unroll
                for (int i = 0; i < 16; ++i) f[i] = 0.f;
            }
#pragma unroll
            for (int kp = 0; kp < 8; ++kp) {
                u32 lo; u32 hi = pack_split(f[2*kp], f[2*kp+1], lo);
                *(u32*)(smem + MS_HI + tid * P_MS + kp * 4) = hi;
                *(u32*)(smem + MS_LO + tid * P_MS + kp * 4) = lo;
            }
        }
        cpy16(smem + W1_HI, g_W1t, 1536, tid);   // hi+lo contiguous
        __syncthreads();

        // ---- L1: [128x16] @ [16x256] -> h ----
        {
            float acc[128];
#pragma unroll
            for (int i = 0; i < 128; ++i) acc[i] = 0.f;
#pragma unroll
            for (int p = 0; p < 3; ++p)
                wgemm<1, 8>(acc,
                    sb + MS_HI + (p == 1 ? 6144u : 0u) + warpM * P_MS, P_MS,
                    sb + W1_HI + (p == 2 ? 12288u : 0u) + wN256 * P_MS, P_MS);
            // epilogue: bias+tanh+split -> h planes
#pragma unroll
            for (int im = 0; im < 2; ++im)
#pragma unroll
            for (int jn = 0; jn < 16; ++jn) {
                const int idx = (im * 16 + jn) * 4;
                const int c = wN256 + 8 * jn + 2 * t;
                const int r = warpM + 16 * im + g;
                u32 lo;
                u32 hi = pack_split(tanh_f(acc[idx+0] + cf[CF_B1 + c]),
                                    tanh_f(acc[idx+1] + cf[CF_B1 + c + 1]), lo);
                *(u32*)(smem + SM_A + r * P_H + c * 2) = hi;
                *(u32*)(smem + SM_A + H_LO + r * P_H + c * 2) = lo;
                hi = pack_split(tanh_f(acc[idx+2] + cf[CF_B1 + c]),
                                tanh_f(acc[idx+3] + cf[CF_B1 + c + 1]), lo);
                *(u32*)(smem + SM_A + (r + 8) * P_H + c * 2) = hi;
                *(u32*)(smem + SM_A + H_LO + (r + 8) * P_H + c * 2) = lo;
            }
        }
        __syncthreads();

        // ---- E1: [128x256] @ [256x128], K chunked by 128 ----
        {
            float acc[64];
#pragma unroll
            for (int i = 0; i < 64; ++i) acc[i] = 0.f;
            for (int c = 0; c < 2; ++c) {
                cpy16(smem + SM_B, g_We1t + c * 69632, 4352, tid);
                __syncthreads();
#pragma unroll
                for (int p = 0; p < 3; ++p)
                    wgemm<8, 4>(acc,
                        sb + SM_A + (p == 1 ? (u32)H_LO : 0u) + warpM * P_H + c * 256, P_H,
                        sb + SM_B + (p == 2 ? (u32)EB_LO : 0u) + wN128 * P_D, P_D);
                __syncthreads();
            }
            // epilogue: tanh -> z partials (E2)
            float zp[24];
#pragma unroll
            for (int i = 0; i < 24; ++i) zp[i] = 0.f;
#pragma unroll
            for (int im = 0; im < 2; ++im)
#pragma unroll
            for (int jn = 0; jn < 8; ++jn) {
                const int idx = (im * 8 + jn) * 4;
                const int c = wN128 + 8 * jn + 2 * t;
                const float h0 = tanh_f(acc[idx+0] + cf[CF_BE1 + c]);
                const float h1 = tanh_f(acc[idx+1] + cf[CF_BE1 + c + 1]);
                const float h2 = tanh_f(acc[idx+2] + cf[CF_BE1 + c]);
                const float h3 = tanh_f(acc[idx+3] + cf[CF_BE1 + c + 1]);
                const float* w0 = &cf[CF_WE2 + c * 6];
                const float* w1 = &cf[CF_WE2 + (c + 1) * 6];
#pragma unroll
                for (int j = 0; j < 6; ++j) {
                    zp[(im*2+0)*6+j] += h0 * w0[j] + h1 * w1[j];
                    zp[(im*2+1)*6+j] += h2 * w0[j] + h3 * w1[j];
                }
            }
#pragma unroll
            for (int i = 0; i < 24; ++i) {
                zp[i] += __shfl_xor_sync(0xffffffffu, zp[i], 1);
                zp[i] += __shfl_xor_sync(0xffffffffu, zp[i], 2);
            }
            if (t == 0) {
#pragma unroll
                for (int im = 0; im < 2; ++im)
#pragma unroll
                for (int rh = 0; rh < 2; ++rh) {
                    const int r = warpM + 16 * im + 8 * rh + g;
#pragma unroll
                    for (int j = 0; j < 6; ++j)
                        cf[CF_ZP + (ngrp * 128 + r) * 6 + j] = zp[(im*2+rh)*6+j];
                }
            }
        }
        __syncthreads();

        // ---- E2 finish + D1: z -> d planes (scalar, tiny) ----
        {
            const int r = tid >> 1;
            const int ih = (tid & 1) * 64;
            float z[6];
#pragma unroll
            for (int j = 0; j < 6; ++j)
                z[j] = tanh_f(cf[CF_ZP + r * 6 + j] + cf[CF_ZP + 768 + r * 6 + j]
                              + cf[CF_BE2 + j]);
#pragma unroll 8
            for (int i = ih; i < ih + 64; i += 2) {
                float d0 = cf[CF_BD1 + i], d1 = cf[CF_BD1 + i + 1];
#pragma unroll
                for (int j = 0; j < 6; ++j) {
                    d0 = fmaf(z[j], cf[CF_WD1 + j * 128 + i],     d0);
                    d1 = fmaf(z[j], cf[CF_WD1 + j * 128 + i + 1], d1);
                }
                u32 lo; u32 hi = pack_split(tanh_f(d0), tanh_f(d1), lo);
                *(u32*)(smem + SM_A + r * P_D + i * 2) = hi;
                *(u32*)(smem + SM_A + D_LO + r * P_D + i * 2) = lo;
            }
        }
        __syncthreads();

        // ---- D2: [128x128] @ [128x256], K chunked by 64 ----
        {
            float acc[128];
#pragma unroll
            for (int i = 0; i < 128; ++i) acc[i] = 0.f;
            for (int c = 0; c < 2; ++c) {
                cpy16(smem + SM_B, g_Wd2t + c * 73728, 4608, tid);
                __syncthreads();
#pragma unroll
                for (int p = 0; p < 3; ++p)
                    wgemm<4, 8>(acc,
                        sb + SM_A + (p == 1 ? (u32)D_LO : 0u) + warpM * P_D + c * 128, P_D,
                        sb + SM_B + (p == 2 ? (u32)DB_LO : 0u) + wN256 * P_DB, P_DB);
                __syncthreads();
            }
            // epilogue: O-layer row partial sums
            float op[4] = {0.f, 0.f, 0.f, 0.f};
#pragma unroll
            for (int im = 0; im < 2; ++im)
#pragma unroll
            for (int jn = 0; jn < 16; ++jn) {
                const int idx = (im * 16 + jn) * 4;
                const int c = wN256 + 8 * jn + 2 * t;
                op[im*2+0] += tanh_f(acc[idx+0] + cf[CF_BD2 + c])     * cf[CF_WO + c]
                            + tanh_f(acc[idx+1] + cf[CF_BD2 + c + 1]) * cf[CF_WO + c + 1];
                op[im*2+1] += tanh_f(acc[idx+2] + cf[CF_BD2 + c])     * cf[CF_WO + c]
                            + tanh_f(acc[idx+3] + cf[CF_BD2 + c + 1]) * cf[CF_WO + c + 1];
            }
#pragma unroll
            for (int i = 0; i < 4; ++i) {
                op[i] += __shfl_xor_sync(0xffffffffu, op[i], 1);
                op[i] += __shfl_xor_sync(0xffffffffu, op[i], 2);
            }
            if (t == 0) {
#pragma unroll
                for (int im = 0; im < 2; ++im)
#pragma unroll
                for (int rh = 0; rh < 2; ++rh)
                    cf[CF_OP + ngrp * 128 + warpM + 16 * im + 8 * rh + g] = op[im*2+rh];
            }
        }
        __syncthreads();

        if (tid < 128) {
            const float v = cf[CF_OP + tid] + cf[CF_OP + 128 + tid] + cf[CF_BO];
            float e;  asm("ex2.approx.f32 %0, %1;" : "=f"(e)  : "f"(-1.442695041f * v));
            float sg; asm("rcp.approx.f32 %0, %1;" : "=f"(sg) : "f"(1.0f + e));
            if (nb + tid < Nn) out[nb + tid] = sg;
        }
    }
}

// ---------------- launch ----------------
extern "C" void kernel_launch(void* const* d_in, const int* in_sizes, int n_in,
                              void* d_out, int out_size)
{
    // order: x, edge_index, edge_attr, W1, b1, We1, be1, We2, be2,
    //        Wd1, bd1, Wd2, bd2, Wo, bo
    const float* edge_attr = (const float*)d_in[2];
    const float* W1  = (const float*)d_in[3];
    const float* b1  = (const float*)d_in[4];
    const float* We1 = (const float*)d_in[5];
    const float* be1 = (const float*)d_in[6];
    const float* We2 = (const float*)d_in[7];
    const float* be2 = (const float*)d_in[8];
    const float* Wd1 = (const float*)d_in[9];
    const float* bd1 = (const float*)d_in[10];
    const float* Wd2 = (const float*)d_in[11];
    const float* bd2 = (const float*)d_in[12];
    const float* Wo  = (const float*)d_in[13];
    const float* bo  = (const float*)d_in[14];
    float* out = (float*)d_out;

    const int Nn = out_size;
    const int ntiles = (Nn + 127) / 128;

    prep_weights<<<304, 256>>>(W1, We1, Wd2);   // 77824 elements

    cudaFuncSetAttribute(gnn_mma_kernel,
                         cudaFuncAttributeMaxDynamicSharedMemorySize, SMEM_BYTES);
    int sms = 148;
    cudaDeviceGetAttribute(&sms, cudaDevAttrMultiProcessorCount, 0);
    const int grid = ntiles < sms ? ntiles : sms;

    gnn_mma_kernel<<<grid, 256, SMEM_BYTES>>>(
        edge_attr, b1, be1, We2, be2, Wd1, bd1, bd2, Wo, bo, out, Nn, ntiles);
}